// round 4
// baseline (speedup 1.0000x reference)
#include <cuda_runtime.h>
#include <math.h>

#define NN 50000
#define NE 600000
#define FEATS 128
#define WSH_STRIDE 132
#define TILE_N 64
#define ROWS_PER_WARP 8
#define ESH_CAP 2048

// smem: Wsh[128][132] + Ash[64][128] + Esh[2048] + Osh[72]
#define GEMM_SMEM ((128 * WSH_STRIDE + TILE_N * FEATS) * 4 + ESH_CAP * 4 + 72 * 4)

#define SCAN_CHUNK 1024
#define NCHUNK ((NN + SCAN_CHUNK - 1) / SCAN_CHUNK)   // 49

// -------------------- device scratch ---------------------------------------
__device__ int g_idx64;
__device__ int g_count[NN];
__device__ int g_off[NN + 1];
__device__ int g_cursor[NN];
__device__ int g_btot[64];
__device__ int g_edges[NE];

// packed fp32x2 FMA (sm_103a; ptxas never auto-emits this)
#define FFMA2(d, a, b) \
    asm("fma.rn.f32x2 %0, %1, %2, %0;" : "+l"(d) : "l"(a), "l"(b))
#define PACKDUP(d, x) \
    asm("mov.b64 %0, {%1, %1};" : "=l"(d) : "r"(__float_as_uint(x)))

__device__ __forceinline__ int load_idx(const void* p, int i) {
    return g_idx64 ? (int)((const long long*)p)[i] : ((const int*)p)[i];
}

// ---------------------------------------------------------------------------
// launch #1: zero counts + detect index dtype
// ---------------------------------------------------------------------------
__global__ void init_kernel(const void* __restrict__ src) {
    int i = blockIdx.x * blockDim.x + threadIdx.x;
    if (i < NN) g_count[i] = 0;
    if (blockIdx.x == 0 && threadIdx.x == 0) {
        const long long* p = (const long long*)src;
        int is64 = 1;
        for (int k = 0; k < 64; k++) {
            long long v = p[k];
            if (v < 0 || v >= NN) { is64 = 0; break; }
        }
        g_idx64 = is64;
    }
}

// ---------------------------------------------------------------------------
// launch #2: histogram, 2 edges per thread
// ---------------------------------------------------------------------------
__global__ void hist_kernel(const void* __restrict__ dst, int nE) {
    int i = (blockIdx.x * blockDim.x + threadIdx.x) * 2;
    if (g_idx64) {
        const long long* p = (const long long*)dst;
        if (i + 1 < nE) {
            longlong2 v = *(const longlong2*)(p + i);
            atomicAdd(&g_count[(int)v.x], 1);
            atomicAdd(&g_count[(int)v.y], 1);
        } else if (i < nE) {
            atomicAdd(&g_count[(int)p[i]], 1);
        }
    } else {
        const int* p = (const int*)dst;
        if (i + 1 < nE) {
            int2 v = *(const int2*)(p + i);
            atomicAdd(&g_count[v.x], 1);
            atomicAdd(&g_count[v.y], 1);
        } else if (i < nE) {
            atomicAdd(&g_count[p[i]], 1);
        }
    }
}

// ---------------------------------------------------------------------------
// launch #3: per-chunk exclusive scan (shuffle-based, 2 barriers)
// ---------------------------------------------------------------------------
__global__ void scanA_kernel() {
    __shared__ int wsum[32];
    int t = threadIdx.x;
    int lane = t & 31, wid = t >> 5;
    int gid = blockIdx.x * SCAN_CHUNK + t;
    int v = (gid < NN) ? g_count[gid] : 0;
    int x = v;
    #pragma unroll
    for (int o = 1; o < 32; o <<= 1) {
        int y = __shfl_up_sync(0xffffffff, x, o);
        if (lane >= o) x += y;
    }
    if (lane == 31) wsum[wid] = x;
    __syncthreads();
    if (wid == 0) {
        int s = wsum[lane];
        #pragma unroll
        for (int o = 1; o < 32; o <<= 1) {
            int y = __shfl_up_sync(0xffffffff, s, o);
            if (lane >= o) s += y;
        }
        wsum[lane] = s;
    }
    __syncthreads();
    int pre = (wid > 0) ? wsum[wid - 1] : 0;
    int incl = x + pre;
    if (gid < NN) g_off[gid] = incl - v;
    if (t == SCAN_CHUNK - 1) g_btot[blockIdx.x] = incl;
}

// ---------------------------------------------------------------------------
// launch #4: each block computes its chunk prefix from g_btot, publishes
// final offsets + cursors (scanB merged in)
// ---------------------------------------------------------------------------
__global__ void scanC_kernel(int nE) {
    __shared__ int sh[64];
    int t = threadIdx.x;
    if (t < 64) sh[t] = (t < NCHUNK && t < blockIdx.x) ? g_btot[t] : 0;
    __syncthreads();
    // tree-reduce 64 -> 1 (sum of totals before my chunk)
    for (int o = 32; o > 0; o >>= 1) {
        if (t < o) sh[t] += sh[t + o];
        __syncthreads();
    }
    int add = sh[0];
    int gid = blockIdx.x * SCAN_CHUNK + t;
    if (gid < NN) {
        int o = g_off[gid] + add;
        g_off[gid] = o;
        g_cursor[gid] = o;
    }
    if (blockIdx.x == 0 && t == 0) g_off[NN] = nE;
}

// ---------------------------------------------------------------------------
// launch #5: fill edge lists, 2 edges per thread
// ---------------------------------------------------------------------------
__global__ void fill_kernel(const void* __restrict__ src,
                            const void* __restrict__ dst, int nE) {
    int i = (blockIdx.x * blockDim.x + threadIdx.x) * 2;
    #pragma unroll
    for (int u = 0; u < 2; u++) {
        int j = i + u;
        if (j < nE) {
            int d = load_idx(dst, j);
            int s = load_idx(src, j);
            int pos = atomicAdd(&g_cursor[d], 1);
            g_edges[pos] = s;
        }
    }
}

// ---------------------------------------------------------------------------
// launch #6: fused gather + GEMM + bias + tanh. Persistent, 2 blocks/SM.
// Each warp: gathers 8 nodes, then computes 8 rows x 4 cols/lane with FFMA2.
// ---------------------------------------------------------------------------
__global__ __launch_bounds__(256, 2) void gcn_fused_kernel(
    const float* __restrict__ feat, const float* __restrict__ W,
    const float* __restrict__ b, float* __restrict__ out, int nNodes) {
    extern __shared__ float sh[];
    float* Wsh = sh;                                  // [128][132]
    float* Ash = sh + 128 * WSH_STRIDE;               // [64][128]
    int*   Esh = (int*)(Ash + TILE_N * FEATS);        // [2048]
    int*   Osh = Esh + ESH_CAP;                       // [72]

    int tid = threadIdx.x;
    int lane = tid & 31;
    int warp = tid >> 5;
    int j0 = lane * 4;
    int lane4 = lane * 4;

    // Load W transposed: Wsh[k][j] = W[j][k]
    for (int idx = tid; idx < 128 * 128; idx += 256) {
        int j = idx >> 7;
        int k = idx & 127;
        Wsh[k * WSH_STRIDE + j] = W[idx];
    }

    float4 bias = *(const float4*)(b + j0);

    for (int tile = blockIdx.x * TILE_N; tile < nNodes; tile += gridDim.x * TILE_N) {
        __syncthreads();   // Ash/Esh reuse (covers Wsh load on iter 0)

        // ---- stage per-node offsets + edge indices ----
        int tend = tile + TILE_N;
        if (tend > nNodes) tend = nNodes;
        int e0t = __ldg(&g_off[tile]);
        int e1t = __ldg(&g_off[tend]);
        int cnt = e1t - e0t;
        bool staged = (cnt <= ESH_CAP);
        if (tid <= TILE_N) {
            int nd = tile + tid;
            if (nd > nNodes) nd = nNodes;
            Osh[tid] = g_off[nd];
        }
        if (staged) {
            for (int i = tid; i < cnt; i += 256) Esh[i] = g_edges[e0t + i];
        }
        __syncthreads();

        // ---- gather: warp handles 8 nodes, lane holds float4 of feats ----
        float4 acc[ROWS_PER_WARP];
        #pragma unroll
        for (int r = 0; r < ROWS_PER_WARP; r++)
            acc[r] = make_float4(0.f, 0.f, 0.f, 0.f);

        #define GATHER_LOOP(IDXP)                                              \
            _Pragma("unroll")                                                  \
            for (int r = 0; r < ROWS_PER_WARP; r++) {                          \
                int node = tile + warp * ROWS_PER_WARP + r;                    \
                if (node < nNodes) {                                           \
                    int eb = Osh[warp * ROWS_PER_WARP + r] - e0t;              \
                    int ee = Osh[warp * ROWS_PER_WARP + r + 1] - e0t;          \
                    for (int e = eb; e < ee; e += 8) {                         \
                        _Pragma("unroll")                                      \
                        for (int u = 0; u < 8; u++) {                          \
                            int j = e + u;                                     \
                            int s = (IDXP)[j < ee ? j : eb];                   \
                            float4 f = *(const float4*)(feat +                 \
                                          (long)s * FEATS + lane4);            \
                            if (j < ee) {                                      \
                                acc[r].x += f.x; acc[r].y += f.y;              \
                                acc[r].z += f.z; acc[r].w += f.w;              \
                            }                                                  \
                        }                                                      \
                    }                                                          \
                }                                                              \
            }

        if (staged) {
            GATHER_LOOP(Esh)
        } else {
            const int* gp = g_edges + e0t;
            GATHER_LOOP(gp)
        }
        #undef GATHER_LOOP

        #pragma unroll
        for (int r = 0; r < ROWS_PER_WARP; r++)
            *(float4*)(Ash + (warp * ROWS_PER_WARP + r) * FEATS + lane4) = acc[r];
        __syncthreads();

        // ---- GEMM: 8 rows x 4 cols per lane, packed f32x2 FMA ----
        const float* abase = Ash + warp * ROWS_PER_WARP * FEATS;

        unsigned long long c[2 * ROWS_PER_WARP];
        #pragma unroll
        for (int r = 0; r < 2 * ROWS_PER_WARP; r++) c[r] = 0;

        #pragma unroll 2
        for (int k4 = 0; k4 < FEATS; k4 += 4) {
            float4 xv[ROWS_PER_WARP];
            #pragma unroll
            for (int r = 0; r < ROWS_PER_WARP; r++)
                xv[r] = *(const float4*)(abase + r * FEATS + k4);
            #pragma unroll
            for (int kk = 0; kk < 4; kk++) {
                ulonglong2 wv =
                    *(const ulonglong2*)(Wsh + (k4 + kk) * WSH_STRIDE + j0);
                #pragma unroll
                for (int r = 0; r < ROWS_PER_WARP; r++) {
                    unsigned long long d;
                    PACKDUP(d, ((const float*)&xv[r])[kk]);
                    FFMA2(c[2 * r], wv.x, d);
                    FFMA2(c[2 * r + 1], wv.y, d);
                }
            }
        }

        int nbase = tile + warp * ROWS_PER_WARP;
        #pragma unroll
        for (int r = 0; r < ROWS_PER_WARP; r++) {
            if (nbase + r < nNodes) {
                float2 lo = *(float2*)&c[2 * r];
                float2 hi = *(float2*)&c[2 * r + 1];
                float4 o;
                o.x = tanhf(lo.x + bias.x);
                o.y = tanhf(lo.y + bias.y);
                o.z = tanhf(hi.x + bias.z);
                o.w = tanhf(hi.y + bias.w);
                *(float4*)(out + (long)(nbase + r) * FEATS + j0) = o;
            }
        }
    }
}

// ---------------------------------------------------------------------------
extern "C" void kernel_launch(void* const* d_in, const int* in_sizes, int n_in,
                              void* d_out, int out_size) {
    const float* feature = (const float*)d_in[0];
    const float* W       = (const float*)d_in[1];
    const float* b       = (const float*)d_in[2];
    const void*  src     = d_in[3];
    const void*  dst     = d_in[4];
    float* out = (float*)d_out;

    int nEdges = in_sizes[3];
    int nNodes = out_size / FEATS;

    init_kernel<<<(NN + 511) / 512, 512>>>(src);
    hist_kernel<<<(nEdges / 2 + 511) / 512, 512>>>(dst, nEdges);
    scanA_kernel<<<NCHUNK, SCAN_CHUNK>>>();
    scanC_kernel<<<NCHUNK, SCAN_CHUNK>>>(nEdges);
    fill_kernel<<<(nEdges / 2 + 511) / 512, 512>>>(src, dst, nEdges);

    cudaFuncSetAttribute(gcn_fused_kernel,
                         cudaFuncAttributeMaxDynamicSharedMemorySize, GEMM_SMEM);
    gcn_fused_kernel<<<296, 256, GEMM_SMEM>>>(feature, W, b, out, nNodes);
}